// round 2
// baseline (speedup 1.0000x reference)
#include <cuda_runtime.h>
#include <cstdint>

// ---------------------------------------------------------------------------
// QMatMul: out[b,h] = A[b,h](2048x64) @ B[b,h](64x2048), fp32 via tf32
// mma.sync (harness compiles for sm_103 non-'a'; tcgen05 unavailable).
// Scales cancel mathematically: (A/sA)@(B/sB)*sA*sB == A@B. Only the trailing
// scalar output element needs sA*sB.
// ---------------------------------------------------------------------------

// SMEM strides (floats). A: stride%32==4 -> a-frag LDS conflict-free.
//                        B: stride%32==8 -> b-frag LDS conflict-free.
static constexpr int AS_STRIDE = 68;    // 64 + 4
static constexpr int BS_STRIDE = 136;   // 128 + 8
static constexpr int AS_FLOATS = 128 * AS_STRIDE;          // 8704
static constexpr int BS_FLOATS = 64 * BS_STRIDE;           // 8704
static constexpr uint32_t SMEM_BYTES = (AS_FLOATS + BS_FLOATS) * 4;  // 69632

static __device__ __forceinline__ uint32_t f2tf32(float x) {
    uint32_t r;
    asm("cvt.rna.tf32.f32 %0, %1;" : "=r"(r) : "f"(x));
    return r;
}

static __device__ __forceinline__ void mma_tf32(
    float& c0, float& c1, float& c2, float& c3,
    uint32_t a0, uint32_t a1, uint32_t a2, uint32_t a3,
    uint32_t b0, uint32_t b1)
{
    asm volatile(
        "mma.sync.aligned.m16n8k8.row.col.f32.tf32.tf32.f32 "
        "{%0,%1,%2,%3}, {%4,%5,%6,%7}, {%8,%9}, {%0,%1,%2,%3};"
        : "+f"(c0), "+f"(c1), "+f"(c2), "+f"(c3)
        : "r"(a0), "r"(a1), "r"(a2), "r"(a3), "r"(b0), "r"(b1));
}

__global__ void __launch_bounds__(256, 2)
qmm_tf32_kernel(const float* __restrict__ A,
                const float* __restrict__ B,
                float* __restrict__ out)
{
    extern __shared__ __align__(128) float smem[];
    float* As = smem;              // [128][AS_STRIDE]  (m-major, k inner)
    float* Bs = smem + AS_FLOATS;  // [64][BS_STRIDE]   (k-major, n inner)

    const int tid = threadIdx.x;
    const int wid = tid >> 5;
    const int lid = tid & 31;
    const int q = lid >> 2;        // 0..7  (groupID)
    const int r = lid & 3;         // 0..3  (thread-in-group)

    const int n_tile = blockIdx.x;   // 0..15
    const int m_tile = blockIdx.y;   // 0..15
    const int bz     = blockIdx.z;   // 0..63

    const size_t batch_in = (size_t)bz * (2048 * 64);
    const float* Ag = A + batch_in + (size_t)m_tile * (128 * 64);
    const float* Bg = B + batch_in + (size_t)n_tile * 128;

    // ---- Global -> SMEM (tf32-rounded), coalesced float4 loads ------------
    {
        const float4* Af4 = (const float4*)Ag;
        #pragma unroll
        for (int it = 0; it < 8; it++) {
            int i = tid + it * 256;              // 0..2047
            float4 v = Af4[i];
            int row = i >> 4;                    // m row
            int c4  = i & 15;                    // 16B chunk along K
            uint32_t* dst = (uint32_t*)(As + row * AS_STRIDE + c4 * 4);
            dst[0] = f2tf32(v.x); dst[1] = f2tf32(v.y);
            dst[2] = f2tf32(v.z); dst[3] = f2tf32(v.w);
        }
        #pragma unroll
        for (int it = 0; it < 8; it++) {
            int i = tid + it * 256;              // 0..2047
            int k  = i >> 5;                     // k row
            int n4 = i & 31;                     // 16B chunk along N
            float4 v = ((const float4*)(Bg + (size_t)k * 2048))[n4];
            uint32_t* dst = (uint32_t*)(Bs + k * BS_STRIDE + n4 * 4);
            dst[0] = f2tf32(v.x); dst[1] = f2tf32(v.y);
            dst[2] = f2tf32(v.z); dst[3] = f2tf32(v.w);
        }
    }
    __syncthreads();

    // ---- Warp tiling: 8 warps = 4(M) x 2(N); warp tile 32x64 --------------
    const int warp_m = wid & 3;          // 0..3 -> 32 rows each
    const int warp_n = wid >> 2;         // 0..1 -> 64 cols each
    const int m0 = warp_m * 32;
    const int n0 = warp_n * 64;

    float acc[2][8][4];
    #pragma unroll
    for (int mt = 0; mt < 2; mt++)
        #pragma unroll
        for (int nt = 0; nt < 8; nt++)
            #pragma unroll
            for (int e = 0; e < 4; e++) acc[mt][nt][e] = 0.0f;

    const uint32_t* Asu = (const uint32_t*)As;
    const uint32_t* Bsu = (const uint32_t*)Bs;

    #pragma unroll
    for (int ks = 0; ks < 8; ks++) {
        const int k0 = ks * 8;

        // A fragments: 2 m-tiles x 4 regs. bank = q*4 + r (+0/+4): distinct.
        uint32_t af[2][4];
        #pragma unroll
        for (int mt = 0; mt < 2; mt++) {
            int rb = (m0 + mt * 16 + q) * AS_STRIDE + k0 + r;
            af[mt][0] = Asu[rb];
            af[mt][1] = Asu[rb + 8 * AS_STRIDE];
            af[mt][2] = Asu[rb + 4];
            af[mt][3] = Asu[rb + 8 * AS_STRIDE + 4];
        }
        // B fragments: 8 n-tiles x 2 regs. bank = r*8 + q (+4 rows): distinct.
        uint32_t bf[8][2];
        #pragma unroll
        for (int nt = 0; nt < 8; nt++) {
            int cb = (k0 + r) * BS_STRIDE + n0 + nt * 8 + q;
            bf[nt][0] = Bsu[cb];
            bf[nt][1] = Bsu[cb + 4 * BS_STRIDE];
        }
        #pragma unroll
        for (int mt = 0; mt < 2; mt++)
            #pragma unroll
            for (int nt = 0; nt < 8; nt++)
                mma_tf32(acc[mt][nt][0], acc[mt][nt][1],
                         acc[mt][nt][2], acc[mt][nt][3],
                         af[mt][0], af[mt][1], af[mt][2], af[mt][3],
                         bf[nt][0], bf[nt][1]);
    }

    // ---- Epilogue: direct STG.64; 8 fully-covered 32B sectors / instr -----
    float* Og = out + (size_t)bz * (2048 * 2048)
                    + (size_t)(m_tile * 128 + m0) * 2048
                    + n_tile * 128 + n0;
    #pragma unroll
    for (int mt = 0; mt < 2; mt++) {
        #pragma unroll
        for (int nt = 0; nt < 8; nt++) {
            int row0 = mt * 16 + q;
            int col  = nt * 8 + 2 * r;
            float2 v0 = make_float2(acc[mt][nt][0], acc[mt][nt][1]);
            float2 v1 = make_float2(acc[mt][nt][2], acc[mt][nt][3]);
            *(float2*)(Og + (size_t)row0 * 2048 + col)       = v0;
            *(float2*)(Og + (size_t)(row0 + 8) * 2048 + col) = v1;
        }
    }
}

// Fill trailing elements (the act_scaling_factor scalar output) with sA*sB.
__global__ void scale_tail_kernel(const float* __restrict__ sA,
                                  const float* __restrict__ sB,
                                  float* __restrict__ out,
                                  long long start, long long total)
{
    long long i = start + (long long)blockIdx.x * blockDim.x + threadIdx.x;
    if (i < total) out[i] = sA[0] * sB[0];
}

extern "C" void kernel_launch(void* const* d_in, const int* in_sizes, int n_in,
                              void* d_out, int out_size)
{
    (void)in_sizes; (void)n_in;
    const float* A  = (const float*)d_in[0];
    const float* sA = (const float*)d_in[1];
    const float* B  = (const float*)d_in[2];
    const float* sB = (const float*)d_in[3];
    float* out = (float*)d_out;

    static bool attr_set = false;
    if (!attr_set) {
        cudaFuncSetAttribute(qmm_tf32_kernel,
                             cudaFuncAttributeMaxDynamicSharedMemorySize,
                             SMEM_BYTES);
        attr_set = true;
    }

    dim3 grid(16, 16, 64);  // (n_tiles, m_tiles, batch*heads)
    qmm_tf32_kernel<<<grid, 256, SMEM_BYTES>>>(A, B, out);

    const long long NMAT = 268435456LL;  // 4*16*2048*2048
    long long extra = (long long)out_size - NMAT;
    if (extra > 0) {
        int blocks = (int)((extra + 127) / 128);
        scale_tail_kernel<<<blocks, 128>>>(sA, sB, out, NMAT,
                                           (long long)out_size);
    }
}